// round 13
// baseline (speedup 1.0000x reference)
#include <cuda_runtime.h>
#include <cuda_fp16.h>
#include <math.h>
#include <stdint.h>

// Problem constants
#define NN 8192
#define DD 256
#define GG 2048
#define BM 128
#define BN 128
#define BK 128                // K elems per chunk (fp8: 128 B per row)
#define NC (DD / BK)          // 2 K-chunks
#define NTILE (NN / BN)       // 64 column tiles
#define NPAIR (NTILE * (NTILE + 1) / 2)   // 2080 upper-tri tiles
#define NBLK (GG / 8)         // 256 group-kernel blocks
#define TPAR 0.04f
// x stored as e4m3 of (8*x): dot_acc = 64 * dot. exp(dot/T) = 2^(acc * log2(e)/(64*T))
#define SCALE8 0.5635527503472513f

__device__ uint8_t g_xq[NN * DD];         // x*8 rounded to e4m3, 2MB
__device__ float   g_partial[NN * NTILE]; // [row][coltile] masked exp rowsum partials
__device__ float   g_block_sum[NBLK];
__device__ int     g_done;                // zero-init; reset by last block each launch

// ------------------------------------------------------------------ helpers
__device__ __forceinline__ float ex2f_(float v) {
    float r; asm("ex2.approx.f32 %0, %1;" : "=f"(r) : "f"(v)); return r;
}
__device__ __forceinline__ uint32_t smem_u32(const void* p) {
    uint32_t a;
    asm("{ .reg .u64 t; cvta.to.shared.u64 t, %1; cvt.u32.u64 %0, t; }" : "=r"(a) : "l"(p));
    return a;
}
__device__ __forceinline__ void ldsm_x4(uint32_t r[4], uint32_t addr) {
    asm volatile("ldmatrix.sync.aligned.m8n8.x4.shared.b16 {%0,%1,%2,%3}, [%4];"
                 : "=r"(r[0]), "=r"(r[1]), "=r"(r[2]), "=r"(r[3]) : "r"(addr));
}
// fp8 e4m3 MMA, K=32, fp32 accumulate
__device__ __forceinline__ void mma_fp8(float c[4], const uint32_t a[4], const uint32_t b0,
                                        const uint32_t b1) {
    asm volatile(
        "mma.sync.aligned.m16n8k32.row.col.f32.e4m3.e4m3.f32 "
        "{%0,%1,%2,%3}, {%4,%5,%6,%7}, {%8,%9}, {%0,%1,%2,%3};"
        : "+f"(c[0]), "+f"(c[1]), "+f"(c[2]), "+f"(c[3])
        : "r"(a[0]), "r"(a[1]), "r"(a[2]), "r"(a[3]), "r"(b0), "r"(b1));
}
// pack two floats -> e4m3x2 (lo = first arg's SECOND operand per cvt convention)
__device__ __forceinline__ uint16_t cvt_e4m3x2(float lo, float hi) {
    uint16_t h;
    asm("cvt.rn.satfinite.e4m3x2.f32 %0, %1, %2;" : "=h"(h) : "f"(hi), "f"(lo));
    return h;
}

// SMEM: 2 stages x (A 16KB + B 16KB) = 64KB + epilogue scratch
#define STAGE_BYTES 32768
#define SM_ROWPART 65536
#define SM_COLPART (65536 + 1024)
#define SMEM_BYTES (65536 + 2048)

// ---------------------------------------------------------------------------
// Kernel 0: quantize x*8 to e4m3 once (16 floats -> 16 bytes per thread)
// ---------------------------------------------------------------------------
__global__ void __launch_bounds__(256) cvt_kernel(const float* __restrict__ x) {
    const int i = (blockIdx.x * 256 + threadIdx.x) * 16;
    float4 v[4];
    #pragma unroll
    for (int u = 0; u < 4; u++) v[u] = *reinterpret_cast<const float4*>(x + i + 4 * u);
    uint32_t o[4];
    #pragma unroll
    for (int u = 0; u < 4; u++) {
        uint16_t p0 = cvt_e4m3x2(v[u].x * 8.f, v[u].y * 8.f);
        uint16_t p1 = cvt_e4m3x2(v[u].z * 8.f, v[u].w * 8.f);
        o[u] = (uint32_t)p0 | ((uint32_t)p1 << 16);
    }
    uint4 out;
    out.x = o[0]; out.y = o[1]; out.z = o[2]; out.w = o[3];
    *reinterpret_cast<uint4*>(g_xq + i) = out;
}

// ---------------------------------------------------------------------------
// Kernel 1: fp8 e4m3 m16n8k32 mma.sync Gram (fp32 accum), upper-tri tiles.
// 128 threads, 4 warps of 64x64, 2 chunks of K=128. Byte-layout identical to
// the validated fp16 kernel (fragments, swizzle, producers all unchanged).
// ---------------------------------------------------------------------------
__global__ void __launch_bounds__(128, 2) gram_mma() {
    extern __shared__ char smem[];
    const uint32_t sb = smem_u32(smem);
    const int tid = threadIdx.x;
    const int lane = tid & 31, wid = tid >> 5;
    const int warp_m = wid & 1;          // 0..1  (64 rows each)
    const int warp_n = wid >> 1;         // 0..1  (64 cols each)

    // linear bid -> upper-tri (bi <= bj)
    const int bid = blockIdx.x;
    int bi = (int)((129.0f - sqrtf(16641.0f - 8.0f * (float)bid)) * 0.5f);
    if (bi > 63) bi = 63;
    while (bi > 0 && (NTILE * bi - (bi * (bi - 1)) / 2) > bid) bi--;
    while ((NTILE * (bi + 1) - ((bi + 1) * bi) / 2) <= bid) bi++;
    const int bj = bi + (bid - (NTILE * bi - (bi * (bi - 1)) / 2));
    const int R0 = bi * BM, C0 = bj * BN;
    const bool diag = (bi == bj);

    float cc[4][8][4];                   // [mtile][ntile][frag] = 128 regs
    #pragma unroll
    for (int m = 0; m < 4; m++)
        #pragma unroll
        for (int n = 0; n < 8; n++)
            #pragma unroll
            for (int f = 0; f < 4; f++) cc[m][n][f] = 0.f;

    // Producer: thread covers rows prow+16*i (i=0..7), 16B-column pq (16 fp8).
    const int prow = tid >> 3;           // 0..15
    const int pq   = tid & 7;
    const uint8_t* srcA0 = g_xq + (size_t)(R0 + prow) * DD + pq * 16;
    const uint8_t* srcB0 = g_xq + (size_t)(C0 + prow) * DD + pq * 16;
    const uint32_t dst0 = (uint32_t)(prow * 128 + ((pq ^ (prow & 7)) << 4));

    // per-lane ldmatrix relative addresses (within a stage) — unchanged mapping
    const int aSel = lane >> 4;
    const int aXor = lane & 7;
    const uint32_t aRel = (uint32_t)((warp_m * 64 + (lane & 15)) * 128);
    const int bSel = (lane >> 3) & 1;
    const int bXor = lane & 7;
    const uint32_t bRel = 16384u +
        (uint32_t)((warp_n * 64 + ((lane >> 4) << 3) + (lane & 7)) * 128);

    // Prologue: chunk 0 -> stage 0
    {
        float4 ra[8], rb[8];
        #pragma unroll
        for (int i = 0; i < 8; i++)
            ra[i] = *reinterpret_cast<const float4*>(srcA0 + (size_t)i * 16 * DD);
        #pragma unroll
        for (int i = 0; i < 8; i++)
            rb[i] = *reinterpret_cast<const float4*>(srcB0 + (size_t)i * 16 * DD);
        #pragma unroll
        for (int i = 0; i < 8; i++) {
            *reinterpret_cast<float4*>(smem + dst0 + i * 2048u)          = ra[i];
            *reinterpret_cast<float4*>(smem + 16384u + dst0 + i * 2048u) = rb[i];
        }
    }

    #pragma unroll
    for (int c = 0; c < NC; c++) {
        const int s = c & 1;
        __syncthreads();   // stage s writes visible; stage s^1 readers done
        const uint32_t sa  = sb + (uint32_t)(s * STAGE_BYTES) + aRel;
        const uint32_t sbb = sb + (uint32_t)(s * STAGE_BYTES) + bRel;
        char* wp = smem + (s ^ 1) * STAGE_BYTES;
        const bool np = (c + 1 < NC);
        const int koff = (c + 1) * BK;   // bytes (1B per elem)

        uint32_t af[4][4], bq[16];
        auto ldfrag = [&](int ks) {      // ks selects 32B = two 16B chunks (2ks, 2ks+1)
            const uint32_t axo = (uint32_t)(((2 * ks + aSel) ^ aXor) << 4);
            const uint32_t bxo = (uint32_t)(((2 * ks + bSel) ^ bXor) << 4);
            #pragma unroll
            for (int p = 0; p < 4; p++) ldsm_x4(&bq[4 * p], sbb + p * 2048u + bxo);
            #pragma unroll
            for (int m = 0; m < 4; m++) ldsm_x4(af[m], sa + m * 2048u + axo);
        };
        auto domma = [&]() {
            #pragma unroll
            for (int m = 0; m < 4; m++)
                #pragma unroll
                for (int n = 0; n < 8; n++)
                    mma_fp8(cc[m][n], af[m], bq[2 * n], bq[2 * n + 1]);
        };

        float4 ra[8];
        if (np) {
            #pragma unroll
            for (int i = 0; i < 8; i++)
                ra[i] = *reinterpret_cast<const float4*>(srcA0 + koff + (size_t)i * 16 * DD);
        }
        ldfrag(0); domma();
        ldfrag(1); domma();
        float4 rb[8];
        if (np) {
            #pragma unroll
            for (int i = 0; i < 8; i++)
                *reinterpret_cast<float4*>(wp + dst0 + i * 2048u) = ra[i];
            #pragma unroll
            for (int i = 0; i < 8; i++)
                rb[i] = *reinterpret_cast<const float4*>(srcB0 + koff + (size_t)i * 16 * DD);
        }
        ldfrag(2); domma();
        ldfrag(3); domma();
        if (np) {
            #pragma unroll
            for (int i = 0; i < 8; i++)
                *reinterpret_cast<float4*>(wp + 16384u + dst0 + i * 2048u) = rb[i];
        }
    }

    // Epilogue: exp(acc * SCALE8), in-group mask, row/col partial sums.
    float* rowpart = reinterpret_cast<float*>(smem + SM_ROWPART);
    float* colpart = reinterpret_cast<float*>(smem + SM_COLPART);
    __syncthreads();

    if (diag) {
        #pragma unroll
        for (int mt = 0; mt < 4; mt++) {
            const int rl = warp_m * 64 + mt * 16 + (lane >> 2);
            const int r_lo = R0 + rl, r_hi = r_lo + 8;
            float lo = 0.f, hi = 0.f;
            #pragma unroll
            for (int nt = 0; nt < 8; nt++) {
                const int c0 = C0 + warp_n * 64 + nt * 8 + 2 * (lane & 3);
                float e;
                e = ex2f_(cc[mt][nt][0] * SCALE8); if ((r_lo >> 2) == (c0 >> 2))       e = 0.f; lo += e;
                e = ex2f_(cc[mt][nt][1] * SCALE8); if ((r_lo >> 2) == ((c0 + 1) >> 2)) e = 0.f; lo += e;
                e = ex2f_(cc[mt][nt][2] * SCALE8); if ((r_hi >> 2) == (c0 >> 2))       e = 0.f; hi += e;
                e = ex2f_(cc[mt][nt][3] * SCALE8); if ((r_hi >> 2) == ((c0 + 1) >> 2)) e = 0.f; hi += e;
            }
            lo += __shfl_xor_sync(0xffffffffu, lo, 1); lo += __shfl_xor_sync(0xffffffffu, lo, 2);
            hi += __shfl_xor_sync(0xffffffffu, hi, 1); hi += __shfl_xor_sync(0xffffffffu, hi, 2);
            if ((lane & 3) == 0) {
                rowpart[rl * 2 + warp_n]       = lo;
                rowpart[(rl + 8) * 2 + warp_n] = hi;
            }
        }
    } else {
        float colacc[8][2];
        #pragma unroll
        for (int nt = 0; nt < 8; nt++) { colacc[nt][0] = 0.f; colacc[nt][1] = 0.f; }
        #pragma unroll
        for (int mt = 0; mt < 4; mt++) {
            const int rl = warp_m * 64 + mt * 16 + (lane >> 2);
            float lo = 0.f, hi = 0.f;
            #pragma unroll
            for (int nt = 0; nt < 8; nt++) {
                float e0 = ex2f_(cc[mt][nt][0] * SCALE8);
                float e1 = ex2f_(cc[mt][nt][1] * SCALE8);
                float e2 = ex2f_(cc[mt][nt][2] * SCALE8);
                float e3 = ex2f_(cc[mt][nt][3] * SCALE8);
                lo += e0 + e1;  hi += e2 + e3;
                colacc[nt][0] += e0 + e2;
                colacc[nt][1] += e1 + e3;
            }
            lo += __shfl_xor_sync(0xffffffffu, lo, 1); lo += __shfl_xor_sync(0xffffffffu, lo, 2);
            hi += __shfl_xor_sync(0xffffffffu, hi, 1); hi += __shfl_xor_sync(0xffffffffu, hi, 2);
            if ((lane & 3) == 0) {
                rowpart[rl * 2 + warp_n]       = lo;
                rowpart[(rl + 8) * 2 + warp_n] = hi;
            }
        }
        #pragma unroll
        for (int nt = 0; nt < 8; nt++) {
            #pragma unroll
            for (int p = 0; p < 2; p++) {
                float v = colacc[nt][p];
                v += __shfl_xor_sync(0xffffffffu, v, 4);
                v += __shfl_xor_sync(0xffffffffu, v, 8);
                v += __shfl_xor_sync(0xffffffffu, v, 16);
                colacc[nt][p] = v;
            }
        }
        if (lane < 4) {
            #pragma unroll
            for (int nt = 0; nt < 8; nt++) {
                const int cl = warp_n * 64 + nt * 8 + 2 * lane;
                colpart[cl * 2 + warp_m]       = colacc[nt][0];
                colpart[(cl + 1) * 2 + warp_m] = colacc[nt][1];
            }
        }
    }
    __syncthreads();
    {
        const float s2 = rowpart[tid * 2 + 0] + rowpart[tid * 2 + 1];
        g_partial[(size_t)(R0 + tid) * NTILE + bj] = s2;
        if (!diag) {
            const float c2 = colpart[tid * 2 + 0] + colpart[tid * 2 + 1];
            g_partial[(size_t)(C0 + tid) * NTILE + bi] = c2;
        }
    }
}

// ---------------------------------------------------------------------------
// Kernel 2: one warp per group (full fp32 positives path) + fused mean
// ---------------------------------------------------------------------------
#define SCALE 36.067376022224085f
__global__ __launch_bounds__(256) void group_kernel(const float* __restrict__ x,
                                                    float* __restrict__ out) {
    __shared__ float wsum[8];
    __shared__ int last;
    const int warp = threadIdx.x >> 5;
    const int lane = threadIdx.x & 31;
    const int g = blockIdx.x * 8 + warp;

    const int pair = lane & 15;
    const int half = lane >> 4;
    const int i = pair >> 2, j = pair & 3;
    const float* xi = x + (size_t)(4 * g + i) * DD + half * 128;
    const float* xj = x + (size_t)(4 * g + j) * DD + half * 128;
    float dot = 0.f;
    #pragma unroll
    for (int k = 0; k < 128; k += 4) {
        float4 a = *reinterpret_cast<const float4*>(xi + k);
        float4 b = *reinterpret_cast<const float4*>(xj + k);
        dot += a.x * b.x + a.y * b.y + a.z * b.z + a.w * b.w;
    }
    dot += __shfl_down_sync(0xffffffffu, dot, 16);

    float en = ex2f_(-dot * SCALE);
    float rowsum = en;
    rowsum += __shfl_xor_sync(0xffffffffu, rowsum, 1);
    rowsum += __shfl_xor_sync(0xffffffffu, rowsum, 2);
    float inv = 0.25f / rowsum;

    float sum_en = en, sum_inv = inv;
    #pragma unroll
    for (int m = 1; m < 16; m <<= 1) {
        sum_en  += __shfl_xor_sync(0xffffffffu, sum_en,  m, 16);
        sum_inv += __shfl_xor_sync(0xffffffffu, sum_inv, m, 16);
    }

    float S = 0.f;
    const float* part = g_partial + (size_t)(4 * g) * NTILE;
    #pragma unroll
    for (int t = 0; t < 4 * NTILE; t += 32) S += part[t + lane];
    #pragma unroll
    for (int m = 1; m < 32; m <<= 1) S += __shfl_xor_sync(0xffffffffu, S, m);

    if (lane == 0) {
        float hard_pos  = -TPAR * logf(sum_en);
        float least_pos =  TPAR * logf(sum_inv);
        float neg       =  TPAR * logf(S);
        float alpha = (hard_pos >= 0.f)
            ? (2.f * least_pos * hard_pos / (hard_pos + least_pos)) : 0.f;
        float margin = alpha * hard_pos + (1.f - alpha) * least_pos;
        float z = (neg - margin) / TPAR;
        float sp = (z > 0.f) ? (z + log1pf(expf(-z))) : log1pf(expf(z));
        wsum[warp] = sp;
    }
    __syncthreads();
    if (threadIdx.x == 0) {
        float bs = 0.f;
        #pragma unroll
        for (int w = 0; w < 8; w++) bs += wsum[w];     // fixed order
        g_block_sum[blockIdx.x] = bs;
        __threadfence();
        int prev = atomicAdd(&g_done, 1);
        last = (prev == NBLK - 1) ? 1 : 0;
    }
    __syncthreads();
    if (last && threadIdx.x < 32) {
        float s = 0.f;
        #pragma unroll
        for (int t = lane; t < NBLK; t += 32) s += g_block_sum[t];   // fixed order
        #pragma unroll
        for (int m = 1; m < 32; m <<= 1) s += __shfl_xor_sync(0xffffffffu, s, m);
        if (lane == 0) { out[0] = s * (1.f / (float)GG); g_done = 0; }
    }
}

// ---------------------------------------------------------------------------
extern "C" void kernel_launch(void* const* d_in, const int* in_sizes, int n_in,
                              void* d_out, int out_size) {
    const float* x = (const float*)d_in[0];
    static int configured = 0;
    if (!configured) {
        cudaFuncSetAttribute(gram_mma, cudaFuncAttributeMaxDynamicSharedMemorySize, SMEM_BYTES);
        configured = 1;
    }
    cvt_kernel<<<NN * DD / 4096, 256>>>(x);
    gram_mma<<<NPAIR, 128, SMEM_BYTES>>>();
    group_kernel<<<NBLK, 256>>>(x, (float*)d_out);
}

// round 14
// speedup vs baseline: 1.0434x; 1.0434x over previous
#include <cuda_runtime.h>
#include <cuda_fp16.h>
#include <math.h>
#include <stdint.h>

// Problem constants
#define NN 8192
#define DD 256
#define GG 2048
#define BM 128
#define BN 128
#define BK 64                 // K halves per chunk (128 B per row)
#define NC (DD / BK)          // 4 K-chunks
#define NTILE (NN / BN)       // 64 column tiles
#define NPAIR (NTILE * (NTILE + 1) / 2)   // 2080 upper-tri tiles
#define NPOS 64               // positives blocks (32 groups each)
#define NBLK (GG / 8)         // 256 slim-group blocks
#define TPAR 0.04f
#define SCALE 36.067376022224085f   // log2(e)/T

__device__ float g_partial[NN * NTILE];  // [row][coltile] masked exp rowsum partials
__device__ float g_mu[GG];               // margin / T per group
__device__ float g_block_sum[NBLK];
__device__ int   g_done;                 // zero-init; reset by last block each launch

// ------------------------------------------------------------------ helpers
__device__ __forceinline__ float ex2f_(float v) {
    float r; asm("ex2.approx.f32 %0, %1;" : "=f"(r) : "f"(v)); return r;
}
__device__ __forceinline__ uint32_t smem_u32(const void* p) {
    uint32_t a;
    asm("{ .reg .u64 t; cvta.to.shared.u64 t, %1; cvt.u32.u64 %0, t; }" : "=r"(a) : "l"(p));
    return a;
}
__device__ __forceinline__ void ldsm_x4(uint32_t r[4], uint32_t addr) {
    asm volatile("ldmatrix.sync.aligned.m8n8.x4.shared.b16 {%0,%1,%2,%3}, [%4];"
                 : "=r"(r[0]), "=r"(r[1]), "=r"(r[2]), "=r"(r[3]) : "r"(addr));
}
// fp16-accumulate MMA (proved rate-equal & rel_err 0.0 in R12)
__device__ __forceinline__ void mma_f16acc(uint32_t c[2], const uint32_t a[4],
                                           const uint32_t b0, const uint32_t b1) {
    asm volatile(
        "mma.sync.aligned.m16n8k16.row.col.f16.f16.f16.f16 "
        "{%0,%1}, {%2,%3,%4,%5}, {%6,%7}, {%0,%1};"
        : "+r"(c[0]), "+r"(c[1])
        : "r"(a[0]), "r"(a[1]), "r"(a[2]), "r"(a[3]), "r"(b0), "r"(b1));
}
__device__ __forceinline__ uint4 pack8(const float4 v0, const float4 v1) {
    __half2 h0 = __floats2half2_rn(v0.x, v0.y);
    __half2 h1 = __floats2half2_rn(v0.z, v0.w);
    __half2 h2 = __floats2half2_rn(v1.x, v1.y);
    __half2 h3 = __floats2half2_rn(v1.z, v1.w);
    uint4 o;
    o.x = *reinterpret_cast<uint32_t*>(&h0);
    o.y = *reinterpret_cast<uint32_t*>(&h1);
    o.z = *reinterpret_cast<uint32_t*>(&h2);
    o.w = *reinterpret_cast<uint32_t*>(&h3);
    return o;
}

// SMEM: 2 stages x (A 16KB + B 16KB) = 64KB + epilogue scratch
#define STAGE_BYTES 32768
#define SM_ROWPART 65536
#define SM_COLPART (65536 + 1024)
#define SMEM_BYTES (65536 + 2048)

// ---------------------------------------------------------------------------
// Kernel 1: fused. bid < NPOS: positives (margin) blocks; else fp16 Gram tile.
// Gram: m16n8k16 mma.sync, f16 accum, fp32->fp16 cvt fused into producer.
// ---------------------------------------------------------------------------
__global__ void __launch_bounds__(128, 2) gram_mma(const float* __restrict__ x) {
    const int tid = threadIdx.x;
    const int lane = tid & 31, wid = tid >> 5;

    // ---------------- positives blocks: margins, runs on fma pipe -------------
    if (blockIdx.x < NPOS) {
        const int pair = lane & 15;
        const int half = lane >> 4;
        const int pi = pair >> 2, pj = pair & 3;
        #pragma unroll 1
        for (int q = 0; q < 8; q++) {
            const int g = blockIdx.x * 32 + wid * 8 + q;
            const float* xi = x + (size_t)(4 * g + pi) * DD + half * 128;
            const float* xj = x + (size_t)(4 * g + pj) * DD + half * 128;
            float dot = 0.f;
            #pragma unroll
            for (int k = 0; k < 128; k += 4) {
                float4 a = *reinterpret_cast<const float4*>(xi + k);
                float4 b = *reinterpret_cast<const float4*>(xj + k);
                dot += a.x * b.x + a.y * b.y + a.z * b.z + a.w * b.w;
            }
            dot += __shfl_down_sync(0xffffffffu, dot, 16);
            float en = ex2f_(-dot * SCALE);
            float rowsum = en;
            rowsum += __shfl_xor_sync(0xffffffffu, rowsum, 1);
            rowsum += __shfl_xor_sync(0xffffffffu, rowsum, 2);
            float inv = 0.25f / rowsum;
            float sum_en = en, sum_inv = inv;
            #pragma unroll
            for (int m = 1; m < 16; m <<= 1) {
                sum_en  += __shfl_xor_sync(0xffffffffu, sum_en,  m, 16);
                sum_inv += __shfl_xor_sync(0xffffffffu, sum_inv, m, 16);
            }
            if (lane == 0) {
                float hard_pos  = -TPAR * logf(sum_en);
                float least_pos =  TPAR * logf(sum_inv);
                float alpha = (hard_pos >= 0.f)
                    ? (2.f * least_pos * hard_pos / (hard_pos + least_pos)) : 0.f;
                float margin = alpha * hard_pos + (1.f - alpha) * least_pos;
                g_mu[g] = margin / TPAR;
            }
        }
        return;
    }

    // ---------------- Gram tile blocks ---------------------------------------
    extern __shared__ char smem[];
    const uint32_t sb = smem_u32(smem);
    const int warp_m = wid & 1;          // 0..1  (64 rows each)
    const int warp_n = wid >> 1;         // 0..1  (64 cols each)

    // linear (bid - NPOS) -> upper-tri (bi <= bj)
    const int bid = blockIdx.x - NPOS;
    int bi = (int)((129.0f - sqrtf(16641.0f - 8.0f * (float)bid)) * 0.5f);
    if (bi > 63) bi = 63;
    while (bi > 0 && (NTILE * bi - (bi * (bi - 1)) / 2) > bid) bi--;
    while ((NTILE * (bi + 1) - ((bi + 1) * bi) / 2) <= bid) bi++;
    const int bj = bi + (bid - (NTILE * bi - (bi * (bi - 1)) / 2));
    const int R0 = bi * BM, C0 = bj * BN;
    const bool diag = (bi == bj);

    uint32_t cc[4][8][2];                // fp16x2 accumulators = 64 regs
    #pragma unroll
    for (int m = 0; m < 4; m++)
        #pragma unroll
        for (int n = 0; n < 8; n++) { cc[m][n][0] = 0u; cc[m][n][1] = 0u; }

    // Producer: thread covers rows prow+16*i (i=0..7), 8-float column pq.
    const int prow = tid >> 3;           // 0..15
    const int pq   = tid & 7;
    const float* srcA0 = x + (size_t)(R0 + prow) * DD + pq * 8;
    const float* srcB0 = x + (size_t)(C0 + prow) * DD + pq * 8;
    const uint32_t dst0 = (uint32_t)(prow * 128 + ((pq ^ (prow & 7)) << 4));

    // per-lane ldmatrix relative addresses (within a stage)
    const int aSel = lane >> 4;
    const int aXor = lane & 7;
    const uint32_t aRel = (uint32_t)((warp_m * 64 + (lane & 15)) * 128);
    const int bSel = (lane >> 3) & 1;
    const int bXor = lane & 7;
    const uint32_t bRel = 16384u +
        (uint32_t)((warp_n * 64 + ((lane >> 4) << 3) + (lane & 7)) * 128);

    // Prologue: chunk 0 -> stage 0 (load fp32, convert, store swizzled)
    {
        uint4 sa[8], sbv[8];
        #pragma unroll
        for (int i = 0; i < 8; i++) {
            float4 v0 = *reinterpret_cast<const float4*>(srcA0 + (size_t)i * 16 * DD);
            float4 v1 = *reinterpret_cast<const float4*>(srcA0 + (size_t)i * 16 * DD + 4);
            sa[i] = pack8(v0, v1);
        }
        #pragma unroll
        for (int i = 0; i < 8; i++) {
            float4 v0 = *reinterpret_cast<const float4*>(srcB0 + (size_t)i * 16 * DD);
            float4 v1 = *reinterpret_cast<const float4*>(srcB0 + (size_t)i * 16 * DD + 4);
            sbv[i] = pack8(v0, v1);
        }
        #pragma unroll
        for (int i = 0; i < 8; i++) {
            *reinterpret_cast<uint4*>(smem + dst0 + i * 2048u)          = sa[i];
            *reinterpret_cast<uint4*>(smem + 16384u + dst0 + i * 2048u) = sbv[i];
        }
    }

    #pragma unroll
    for (int c = 0; c < NC; c++) {
        const int s = c & 1;
        __syncthreads();   // stage s writes visible; stage s^1 readers done
        const uint32_t sa  = sb + (uint32_t)(s * STAGE_BYTES) + aRel;
        const uint32_t sbb = sb + (uint32_t)(s * STAGE_BYTES) + bRel;
        char* wp = smem + (s ^ 1) * STAGE_BYTES;
        const bool np = (c + 1 < NC);
        const int koff = (c + 1) * BK;   // floats

        uint32_t af[4][4], bq[16];
        auto ldfrag = [&](int ks) {
            const uint32_t axo = (uint32_t)(((2 * ks + aSel) ^ aXor) << 4);
            const uint32_t bxo = (uint32_t)(((2 * ks + bSel) ^ bXor) << 4);
            #pragma unroll
            for (int p = 0; p < 4; p++) ldsm_x4(&bq[4 * p], sbb + p * 2048u + bxo);
            #pragma unroll
            for (int m = 0; m < 4; m++) ldsm_x4(af[m], sa + m * 2048u + axo);
        };
        auto domma = [&]() {
            #pragma unroll
            for (int m = 0; m < 4; m++)
                #pragma unroll
                for (int n = 0; n < 8; n++)
                    mma_f16acc(cc[m][n], af[m], bq[2 * n], bq[2 * n + 1]);
        };

        uint4 su[8];
        if (np) {
            #pragma unroll
            for (int i = 0; i < 8; i++) {
                float4 v0 = *reinterpret_cast<const float4*>(srcA0 + koff + (size_t)i * 16 * DD);
                float4 v1 = *reinterpret_cast<const float4*>(srcA0 + koff + (size_t)i * 16 * DD + 4);
                su[i] = pack8(v0, v1);
            }
        }
        ldfrag(0); domma();
        ldfrag(1); domma();
        if (np) {
            #pragma unroll
            for (int i = 0; i < 8; i++)
                *reinterpret_cast<uint4*>(wp + dst0 + i * 2048u) = su[i];
            #pragma unroll
            for (int i = 0; i < 8; i++) {
                float4 v0 = *reinterpret_cast<const float4*>(srcB0 + koff + (size_t)i * 16 * DD);
                float4 v1 = *reinterpret_cast<const float4*>(srcB0 + koff + (size_t)i * 16 * DD + 4);
                su[i] = pack8(v0, v1);
            }
        }
        ldfrag(2); domma();
        ldfrag(3); domma();
        if (np) {
            #pragma unroll
            for (int i = 0; i < 8; i++)
                *reinterpret_cast<uint4*>(wp + 16384u + dst0 + i * 2048u) = su[i];
        }
    }

    // Epilogue: unpack half2 -> fp32 exp/mask/row+col sums (R12-validated).
    float* rowpart = reinterpret_cast<float*>(smem + SM_ROWPART);
    float* colpart = reinterpret_cast<float*>(smem + SM_COLPART);
    __syncthreads();

    if (diag) {
        #pragma unroll
        for (int mt = 0; mt < 4; mt++) {
            const int rl = warp_m * 64 + mt * 16 + (lane >> 2);
            const int r_lo = R0 + rl, r_hi = r_lo + 8;
            float lo = 0.f, hi = 0.f;
            #pragma unroll
            for (int nt = 0; nt < 8; nt++) {
                const int c0 = C0 + warp_n * 64 + nt * 8 + 2 * (lane & 3);
                float2 v0 = __half22float2(*reinterpret_cast<__half2*>(&cc[mt][nt][0]));
                float2 v1 = __half22float2(*reinterpret_cast<__half2*>(&cc[mt][nt][1]));
                float e;
                e = ex2f_(v0.x * SCALE); if ((r_lo >> 2) == (c0 >> 2))       e = 0.f; lo += e;
                e = ex2f_(v0.y * SCALE); if ((r_lo >> 2) == ((c0 + 1) >> 2)) e = 0.f; lo += e;
                e = ex2f_(v1.x * SCALE); if ((r_hi >> 2) == (c0 >> 2))       e = 0.f; hi += e;
                e = ex2f_(v1.y * SCALE); if ((r_hi >> 2) == ((c0 + 1) >> 2)) e = 0.f; hi += e;
            }
            lo += __shfl_xor_sync(0xffffffffu, lo, 1); lo += __shfl_xor_sync(0xffffffffu, lo, 2);
            hi += __shfl_xor_sync(0xffffffffu, hi, 1); hi += __shfl_xor_sync(0xffffffffu, hi, 2);
            if ((lane & 3) == 0) {
                rowpart[rl * 2 + warp_n]       = lo;
                rowpart[(rl + 8) * 2 + warp_n] = hi;
            }
        }
    } else {
        float colacc[8][2];
        #pragma unroll
        for (int nt = 0; nt < 8; nt++) { colacc[nt][0] = 0.f; colacc[nt][1] = 0.f; }
        #pragma unroll
        for (int mt = 0; mt < 4; mt++) {
            const int rl = warp_m * 64 + mt * 16 + (lane >> 2);
            float lo = 0.f, hi = 0.f;
            #pragma unroll
            for (int nt = 0; nt < 8; nt++) {
                float2 v0 = __half22float2(*reinterpret_cast<__half2*>(&cc[mt][nt][0]));
                float2 v1 = __half22float2(*reinterpret_cast<__half2*>(&cc[mt][nt][1]));
                float e0 = ex2f_(v0.x * SCALE);
                float e1 = ex2f_(v0.y * SCALE);
                float e2 = ex2f_(v1.x * SCALE);
                float e3 = ex2f_(v1.y * SCALE);
                lo += e0 + e1;  hi += e2 + e3;
                colacc[nt][0] += e0 + e2;
                colacc[nt][1] += e1 + e3;
            }
            lo += __shfl_xor_sync(0xffffffffu, lo, 1); lo += __shfl_xor_sync(0xffffffffu, lo, 2);
            hi += __shfl_xor_sync(0xffffffffu, hi, 1); hi += __shfl_xor_sync(0xffffffffu, hi, 2);
            if ((lane & 3) == 0) {
                rowpart[rl * 2 + warp_n]       = lo;
                rowpart[(rl + 8) * 2 + warp_n] = hi;
            }
        }
        #pragma unroll
        for (int nt = 0; nt < 8; nt++) {
            #pragma unroll
            for (int p = 0; p < 2; p++) {
                float v = colacc[nt][p];
                v += __shfl_xor_sync(0xffffffffu, v, 4);
                v += __shfl_xor_sync(0xffffffffu, v, 8);
                v += __shfl_xor_sync(0xffffffffu, v, 16);
                colacc[nt][p] = v;
            }
        }
        if (lane < 4) {
            #pragma unroll
            for (int nt = 0; nt < 8; nt++) {
                const int cl = warp_n * 64 + nt * 8 + 2 * lane;
                colpart[cl * 2 + warp_m]       = colacc[nt][0];
                colpart[(cl + 1) * 2 + warp_m] = colacc[nt][1];
            }
        }
    }
    __syncthreads();
    {
        const float s2 = rowpart[tid * 2 + 0] + rowpart[tid * 2 + 1];
        g_partial[(size_t)(R0 + tid) * NTILE + bj] = s2;
        if (!diag) {
            const float c2 = colpart[tid * 2 + 0] + colpart[tid * 2 + 1];
            g_partial[(size_t)(C0 + tid) * NTILE + bi] = c2;
        }
    }
}

// ---------------------------------------------------------------------------
// Kernel 2 (slim): per group sum partials + softplus(log S - mu) + fused mean
// ---------------------------------------------------------------------------
__global__ __launch_bounds__(256) void group_slim(float* __restrict__ out) {
    __shared__ float wsum[8];
    __shared__ int last;
    const int warp = threadIdx.x >> 5;
    const int lane = threadIdx.x & 31;
    const int g = blockIdx.x * 8 + warp;

    float S = 0.f;
    const float* part = g_partial + (size_t)(4 * g) * NTILE;
    #pragma unroll
    for (int t = 0; t < 4 * NTILE; t += 32) S += part[t + lane];
    #pragma unroll
    for (int m = 1; m < 32; m <<= 1) S += __shfl_xor_sync(0xffffffffu, S, m);

    if (lane == 0) {
        float z = logf(S) - g_mu[g];     // (neg - margin)/T
        float sp = (z > 0.f) ? (z + log1pf(expf(-z))) : log1pf(expf(z));
        wsum[warp] = sp;
    }
    __syncthreads();
    if (threadIdx.x == 0) {
        float bs = 0.f;
        #pragma unroll
        for (int w = 0; w < 8; w++) bs += wsum[w];     // fixed order
        g_block_sum[blockIdx.x] = bs;
        __threadfence();
        int prev = atomicAdd(&g_done, 1);
        last = (prev == NBLK - 1) ? 1 : 0;
    }
    __syncthreads();
    if (last && threadIdx.x < 32) {
        float s = 0.f;
        #pragma unroll
        for (int t = lane; t < NBLK; t += 32) s += g_block_sum[t];   // fixed order
        #pragma unroll
        for (int m = 1; m < 32; m <<= 1) s += __shfl_xor_sync(0xffffffffu, s, m);
        if (lane == 0) { out[0] = s * (1.f / (float)GG); g_done = 0; }
    }
}

// ---------------------------------------------------------------------------
extern "C" void kernel_launch(void* const* d_in, const int* in_sizes, int n_in,
                              void* d_out, int out_size) {
    const float* x = (const float*)d_in[0];
    static int configured = 0;
    if (!configured) {
        cudaFuncSetAttribute(gram_mma, cudaFuncAttributeMaxDynamicSharedMemorySize, SMEM_BYTES);
        configured = 1;
    }
    gram_mma<<<NPOS + NPAIR, 128, SMEM_BYTES>>>(x);
    group_slim<<<NBLK, 256>>>((float*)d_out);
}

// round 15
// speedup vs baseline: 1.3653x; 1.3085x over previous
#include <cuda_runtime.h>
#include <cuda_fp16.h>
#include <math.h>
#include <stdint.h>

// Problem constants
#define NN 8192
#define DD 256
#define GG 2048
#define BM 128
#define BN 128
#define BK 64                 // K elems per chunk (fp16: 128 B per row)
#define NC (DD / BK)          // 4 K-chunks
#define NTILE (NN / BN)       // 64 column tiles
#define NPAIR (NTILE * (NTILE + 1) / 2)   // 2080 upper-tri tiles
#define NPOS 64               // positives blocks (32 groups each)
#define NBLK (GG / 8)         // 256 slim-group blocks
#define TPAR 0.04f
#define SCALE 36.067376022224085f   // log2(e)/T

__device__ __half g_xh[NN * DD];          // x rounded to fp16 (RN), 4MB
__device__ float  g_partial[NN * NTILE];  // [row][coltile] masked exp rowsum partials
__device__ float  g_mu[GG];               // margin / T per group
__device__ float  g_block_sum[NBLK];
__device__ int    g_done;                 // zero-init; reset by last block each launch

// ------------------------------------------------------------------ helpers
__device__ __forceinline__ float ex2f_(float v) {
    float r; asm("ex2.approx.f32 %0, %1;" : "=f"(r) : "f"(v)); return r;
}
__device__ __forceinline__ uint32_t smem_u32(const void* p) {
    uint32_t a;
    asm("{ .reg .u64 t; cvta.to.shared.u64 t, %1; cvt.u32.u64 %0, t; }" : "=r"(a) : "l"(p));
    return a;
}
__device__ __forceinline__ void ldsm_x4(uint32_t r[4], uint32_t addr) {
    asm volatile("ldmatrix.sync.aligned.m8n8.x4.shared.b16 {%0,%1,%2,%3}, [%4];"
                 : "=r"(r[0]), "=r"(r[1]), "=r"(r[2]), "=r"(r[3]) : "r"(addr));
}
// fp16-accumulate MMA (rate-equal to f32-acc; rel_err 0.0 measured in R12)
__device__ __forceinline__ void mma_f16acc(uint32_t c[2], const uint32_t a[4],
                                           const uint32_t b0, const uint32_t b1) {
    asm volatile(
        "mma.sync.aligned.m16n8k16.row.col.f16.f16.f16.f16 "
        "{%0,%1}, {%2,%3,%4,%5}, {%6,%7}, {%0,%1};"
        : "+r"(c[0]), "+r"(c[1])
        : "r"(a[0]), "r"(a[1]), "r"(a[2]), "r"(a[3]), "r"(b0), "r"(b1));
}

// SMEM: 2 stages x (A 16KB + B 16KB) = 64KB + epilogue scratch
#define STAGE_BYTES 32768
#define SM_ROWPART 65536
#define SM_COLPART (65536 + 1024)
#define SMEM_BYTES (65536 + 2048)

// ---------------------------------------------------------------------------
// Kernel 0: round x to fp16 (RN) once
// ---------------------------------------------------------------------------
__global__ void __launch_bounds__(256) cvt_kernel(const float* __restrict__ x) {
    const int i = (blockIdx.x * 256 + threadIdx.x) * 8;
    float4 a = *reinterpret_cast<const float4*>(x + i);
    float4 b = *reinterpret_cast<const float4*>(x + i + 4);
    __half2 h0 = __floats2half2_rn(a.x, a.y);
    __half2 h1 = __floats2half2_rn(a.z, a.w);
    __half2 h2 = __floats2half2_rn(b.x, b.y);
    __half2 h3 = __floats2half2_rn(b.z, b.w);
    uint4 o;
    o.x = *reinterpret_cast<uint32_t*>(&h0);
    o.y = *reinterpret_cast<uint32_t*>(&h1);
    o.z = *reinterpret_cast<uint32_t*>(&h2);
    o.w = *reinterpret_cast<uint32_t*>(&h3);
    *reinterpret_cast<uint4*>(g_xh + i) = o;
}

// ---------------------------------------------------------------------------
// Kernel 1: bid < NPOS: positives (margin) blocks on the fma pipe.
//           else: fp16 m16n8k16 mma.sync Gram (f16 accum), upper-tri tiles —
//           byte-for-byte the R12 floor configuration.
// ---------------------------------------------------------------------------
__global__ void __launch_bounds__(128, 3) gram_mma(const float* __restrict__ x) {
    const int tid = threadIdx.x;
    const int lane = tid & 31, wid = tid >> 5;

    if (blockIdx.x < NPOS) {
        // ---- positives: 32 groups per block (8 per warp), exact fp32 path ----
        const int pair = lane & 15;
        const int half = lane >> 4;
        const int pi = pair >> 2, pj = pair & 3;
        #pragma unroll 1
        for (int q = 0; q < 8; q++) {
            const int g = blockIdx.x * 32 + wid * 8 + q;
            const float* xi = x + (size_t)(4 * g + pi) * DD + half * 128;
            const float* xj = x + (size_t)(4 * g + pj) * DD + half * 128;
            float dot = 0.f;
            #pragma unroll
            for (int k = 0; k < 128; k += 4) {
                float4 a = *reinterpret_cast<const float4*>(xi + k);
                float4 b = *reinterpret_cast<const float4*>(xj + k);
                dot += a.x * b.x + a.y * b.y + a.z * b.z + a.w * b.w;
            }
            dot += __shfl_down_sync(0xffffffffu, dot, 16);
            float en = ex2f_(-dot * SCALE);
            float rowsum = en;
            rowsum += __shfl_xor_sync(0xffffffffu, rowsum, 1);
            rowsum += __shfl_xor_sync(0xffffffffu, rowsum, 2);
            float inv = 0.25f / rowsum;
            float sum_en = en, sum_inv = inv;
            #pragma unroll
            for (int m = 1; m < 16; m <<= 1) {
                sum_en  += __shfl_xor_sync(0xffffffffu, sum_en,  m, 16);
                sum_inv += __shfl_xor_sync(0xffffffffu, sum_inv, m, 16);
            }
            if (lane == 0) {
                float hard_pos  = -TPAR * logf(sum_en);
                float least_pos =  TPAR * logf(sum_inv);
                float alpha = (hard_pos >= 0.f)
                    ? (2.f * least_pos * hard_pos / (hard_pos + least_pos)) : 0.f;
                float margin = alpha * hard_pos + (1.f - alpha) * least_pos;
                g_mu[g] = margin / TPAR;
            }
        }
        return;
    }

    // ---- Gram tile (R12 floor config) ----
    extern __shared__ char smem[];
    const uint32_t sb = smem_u32(smem);
    const int warp_m = wid & 1;          // 0..1  (64 rows each)
    const int warp_n = wid >> 1;         // 0..1  (64 cols each)

    const int bid = blockIdx.x - NPOS;
    int bi = (int)((129.0f - sqrtf(16641.0f - 8.0f * (float)bid)) * 0.5f);
    if (bi > 63) bi = 63;
    while (bi > 0 && (NTILE * bi - (bi * (bi - 1)) / 2) > bid) bi--;
    while ((NTILE * (bi + 1) - ((bi + 1) * bi) / 2) <= bid) bi++;
    const int bj = bi + (bid - (NTILE * bi - (bi * (bi - 1)) / 2));
    const int R0 = bi * BM, C0 = bj * BN;
    const bool diag = (bi == bj);

    uint32_t cc[4][8][2];                // fp16x2 accumulators = 64 regs
    #pragma unroll
    for (int m = 0; m < 4; m++)
        #pragma unroll
        for (int n = 0; n < 8; n++) { cc[m][n][0] = 0u; cc[m][n][1] = 0u; }

    const int prow = tid >> 3;           // 0..15
    const int pq   = tid & 7;
    const __half* srcA0 = g_xh + (size_t)(R0 + prow) * DD + pq * 8;
    const __half* srcB0 = g_xh + (size_t)(C0 + prow) * DD + pq * 8;
    const uint32_t dst0 = (uint32_t)(prow * 128 + ((pq ^ (prow & 7)) << 4));

    const int aSel = lane >> 4;
    const int aXor = lane & 7;
    const uint32_t aRel = (uint32_t)((warp_m * 64 + (lane & 15)) * 128);
    const int bSel = (lane >> 3) & 1;
    const int bXor = lane & 7;
    const uint32_t bRel = 16384u +
        (uint32_t)((warp_n * 64 + ((lane >> 4) << 3) + (lane & 7)) * 128);

    // Prologue: chunk 0 -> stage 0
    {
        float4 ra[8], rb[8];
        #pragma unroll
        for (int i = 0; i < 8; i++)
            ra[i] = *reinterpret_cast<const float4*>(srcA0 + (size_t)i * 16 * DD);
        #pragma unroll
        for (int i = 0; i < 8; i++)
            rb[i] = *reinterpret_cast<const float4*>(srcB0 + (size_t)i * 16 * DD);
        #pragma unroll
        for (int i = 0; i < 8; i++) {
            *reinterpret_cast<float4*>(smem + dst0 + i * 2048u)          = ra[i];
            *reinterpret_cast<float4*>(smem + 16384u + dst0 + i * 2048u) = rb[i];
        }
    }

    #pragma unroll
    for (int c = 0; c < NC; c++) {
        const int s = c & 1;
        __syncthreads();
        const uint32_t sa  = sb + (uint32_t)(s * STAGE_BYTES) + aRel;
        const uint32_t sbb = sb + (uint32_t)(s * STAGE_BYTES) + bRel;
        char* wp = smem + (s ^ 1) * STAGE_BYTES;
        const bool np = (c + 1 < NC);
        const int koff = (c + 1) * BK;   // halves

        uint32_t af[4][4], bq[16];
        auto ldfrag = [&](int ks) {
            const uint32_t axo = (uint32_t)(((2 * ks + aSel) ^ aXor) << 4);
            const uint32_t bxo = (uint32_t)(((2 * ks + bSel) ^ bXor) << 4);
            #pragma unroll
            for (int p = 0; p < 4; p++) ldsm_x4(&bq[4 * p], sbb + p * 2048u + bxo);
            #pragma unroll
            for (int m = 0; m < 4; m++) ldsm_x4(af[m], sa + m * 2048u + axo);
        };
        auto domma = [&]() {
            #pragma unroll
            for (int m = 0; m < 4; m++)
                #pragma unroll
                for (int n = 0; n < 8; n++)
                    mma_f16acc(cc[m][n], af[m], bq[2 * n], bq[2 * n + 1]);
        };

        float4 ra[8];
        if (np) {
            #pragma unroll
            for (int i = 0; i < 8; i++)
                ra[i] = *reinterpret_cast<const float4*>(srcA0 + koff + (size_t)i * 16 * DD);
        }
        ldfrag(0); domma();
        ldfrag(1); domma();
        float4 rb[8];
        if (np) {
            #pragma unroll
            for (int i = 0; i < 8; i++)
                *reinterpret_cast<float4*>(wp + dst0 + i * 2048u) = ra[i];
            #pragma unroll
            for (int i = 0; i < 8; i++)
                rb[i] = *reinterpret_cast<const float4*>(srcB0 + koff + (size_t)i * 16 * DD);
        }
        ldfrag(2); domma();
        ldfrag(3); domma();
        if (np) {
            #pragma unroll
            for (int i = 0; i < 8; i++)
                *reinterpret_cast<float4*>(wp + 16384u + dst0 + i * 2048u) = rb[i];
        }
    }

    // Epilogue: unpack half2 -> fp32 exp/mask/row+col sums
    float* rowpart = reinterpret_cast<float*>(smem + SM_ROWPART);
    float* colpart = reinterpret_cast<float*>(smem + SM_COLPART);
    __syncthreads();

    if (diag) {
        #pragma unroll
        for (int mt = 0; mt < 4; mt++) {
            const int rl = warp_m * 64 + mt * 16 + (lane >> 2);
            const int r_lo = R0 + rl, r_hi = r_lo + 8;
            float lo = 0.f, hi = 0.f;
            #pragma unroll
            for (int nt = 0; nt < 8; nt++) {
                const int c0 = C0 + warp_n * 64 + nt * 8 + 2 * (lane & 3);
                float2 v0 = __half22float2(*reinterpret_cast<__half2*>(&cc[mt][nt][0]));
                float2 v1 = __half22float2(*reinterpret_cast<__half2*>(&cc[mt][nt][1]));
                float e;
                e = ex2f_(v0.x * SCALE); if ((r_lo >> 2) == (c0 >> 2))       e = 0.f; lo += e;
                e = ex2f_(v0.y * SCALE); if ((r_lo >> 2) == ((c0 + 1) >> 2)) e = 0.f; lo += e;
                e = ex2f_(v1.x * SCALE); if ((r_hi >> 2) == (c0 >> 2))       e = 0.f; hi += e;
                e = ex2f_(v1.y * SCALE); if ((r_hi >> 2) == ((c0 + 1) >> 2)) e = 0.f; hi += e;
            }
            lo += __shfl_xor_sync(0xffffffffu, lo, 1); lo += __shfl_xor_sync(0xffffffffu, lo, 2);
            hi += __shfl_xor_sync(0xffffffffu, hi, 1); hi += __shfl_xor_sync(0xffffffffu, hi, 2);
            if ((lane & 3) == 0) {
                rowpart[rl * 2 + warp_n]       = lo;
                rowpart[(rl + 8) * 2 + warp_n] = hi;
            }
        }
    } else {
        float colacc[8][2];
        #pragma unroll
        for (int nt = 0; nt < 8; nt++) { colacc[nt][0] = 0.f; colacc[nt][1] = 0.f; }
        #pragma unroll
        for (int mt = 0; mt < 4; mt++) {
            const int rl = warp_m * 64 + mt * 16 + (lane >> 2);
            float lo = 0.f, hi = 0.f;
            #pragma unroll
            for (int nt = 0; nt < 8; nt++) {
                float2 v0 = __half22float2(*reinterpret_cast<__half2*>(&cc[mt][nt][0]));
                float2 v1 = __half22float2(*reinterpret_cast<__half2*>(&cc[mt][nt][1]));
                float e0 = ex2f_(v0.x * SCALE);
                float e1 = ex2f_(v0.y * SCALE);
                float e2 = ex2f_(v1.x * SCALE);
                float e3 = ex2f_(v1.y * SCALE);
                lo += e0 + e1;  hi += e2 + e3;
                colacc[nt][0] += e0 + e2;
                colacc[nt][1] += e1 + e3;
            }
            lo += __shfl_xor_sync(0xffffffffu, lo, 1); lo += __shfl_xor_sync(0xffffffffu, lo, 2);
            hi += __shfl_xor_sync(0xffffffffu, hi, 1); hi += __shfl_xor_sync(0xffffffffu, hi, 2);
            if ((lane & 3) == 0) {
                rowpart[rl * 2 + warp_n]       = lo;
                rowpart[(rl + 8) * 2 + warp_n] = hi;
            }
        }
        #pragma unroll
        for (int nt = 0; nt < 8; nt++) {
            #pragma unroll
            for (int p = 0; p < 2; p++) {
                float v = colacc[nt][p];
                v += __shfl_xor_sync(0xffffffffu, v, 4);
                v += __shfl_xor_sync(0xffffffffu, v, 8);
                v += __shfl_xor_sync(0xffffffffu, v, 16);
                colacc[nt][p] = v;
            }
        }
        if (lane < 4) {
            #pragma unroll
            for (int nt = 0; nt < 8; nt++) {
                const int cl = warp_n * 64 + nt * 8 + 2 * lane;
                colpart[cl * 2 + warp_m]       = colacc[nt][0];
                colpart[(cl + 1) * 2 + warp_m] = colacc[nt][1];
            }
        }
    }
    __syncthreads();
    {
        const float s2 = rowpart[tid * 2 + 0] + rowpart[tid * 2 + 1];
        g_partial[(size_t)(R0 + tid) * NTILE + bj] = s2;
        if (!diag) {
            const float c2 = colpart[tid * 2 + 0] + colpart[tid * 2 + 1];
            g_partial[(size_t)(C0 + tid) * NTILE + bi] = c2;
        }
    }
}

// ---------------------------------------------------------------------------
// Kernel 2 (slim): per group sum 256 partials (float4) + softplus + fused mean
// ---------------------------------------------------------------------------
__global__ __launch_bounds__(256) void group_slim(float* __restrict__ out) {
    __shared__ float wsum[8];
    __shared__ int last;
    const int warp = threadIdx.x >> 5;
    const int lane = threadIdx.x & 31;
    const int g = blockIdx.x * 8 + warp;

    const float4* part = reinterpret_cast<const float4*>(g_partial + (size_t)(4 * g) * NTILE);
    float4 p0 = part[lane];
    float4 p1 = part[lane + 32];
    float S = (p0.x + p0.y) + (p0.z + p0.w) + (p1.x + p1.y) + (p1.z + p1.w);
    #pragma unroll
    for (int m = 1; m < 32; m <<= 1) S += __shfl_xor_sync(0xffffffffu, S, m);

    if (lane == 0) {
        float z = logf(S) - g_mu[g];     // (neg - margin)/T
        float sp = (z > 0.f) ? (z + log1pf(expf(-z))) : log1pf(expf(z));
        wsum[warp] = sp;
    }
    __syncthreads();
    if (threadIdx.x == 0) {
        float bs = 0.f;
        #pragma unroll
        for (int w = 0; w < 8; w++) bs += wsum[w];     // fixed order
        g_block_sum[blockIdx.x] = bs;
        __threadfence();
        int prev = atomicAdd(&g_done, 1);
        last = (prev == NBLK - 1) ? 1 : 0;
    }
    __syncthreads();
    if (last && threadIdx.x < 32) {
        float s = 0.f;
        #pragma unroll
        for (int t = lane; t < NBLK; t += 32) s += g_block_sum[t];   // fixed order
        #pragma unroll
        for (int m = 1; m < 32; m <<= 1) s += __shfl_xor_sync(0xffffffffu, s, m);
        if (lane == 0) { out[0] = s * (1.f / (float)GG); g_done = 0; }
    }
}

// ---------------------------------------------------------------------------
extern "C" void kernel_launch(void* const* d_in, const int* in_sizes, int n_in,
                              void* d_out, int out_size) {
    const float* x = (const float*)d_in[0];
    static int configured = 0;
    if (!configured) {
        cudaFuncSetAttribute(gram_mma, cudaFuncAttributeMaxDynamicSharedMemorySize, SMEM_BYTES);
        configured = 1;
    }
    cvt_kernel<<<NN * DD / 2048, 256>>>(x);
    gram_mma<<<NPOS + NPAIR, 128, SMEM_BYTES>>>(x);
    group_slim<<<NBLK, 256>>>((float*)d_out);
}